// round 6
// baseline (speedup 1.0000x reference)
#include <cuda_runtime.h>
#include <math.h>

#define NB 32
#define NN 1024
#define L2E 1.4426950408889634f

// Scratch vectors (device globals: no allocation allowed in kernel_launch).
// Everything kept in log2 domain: R = r*log2(e), C = c*log2(e).
__device__ float d_rs[NB * NN];
__device__ float d_cs[NB * NN];

// ---------------------------------------------------------------------------
// cs = 0
__global__ __launch_bounds__(256) void zero_cs_kernel() {
    d_cs[blockIdx.x * 256 + threadIdx.x] = 0.0f;
}

// ---------------------------------------------------------------------------
// Row pass: R[b,i] = -log2( sum_j exp2( g[b,i,j]*L2E + C[b,j] ) )
// One warp per row; 8 rows (one batch only, 1024%8==0) per 256-thread CTA.
// C[b,:] staged in shared once per CTA.
__global__ __launch_bounds__(256) void row_pass_kernel(const float* __restrict__ g) {
    __shared__ float4 s_cs[NN / 4];

    const int row0 = blockIdx.x * 8;
    const int b    = row0 >> 10;

    // stage cs[b, 0..1023] -> smem (256 x float4)
    s_cs[threadIdx.x] = ((const float4*)(d_cs + (b << 10)))[threadIdx.x];
    __syncthreads();

    const int warp = threadIdx.x >> 5;
    const int lane = threadIdx.x & 31;
    const int row  = row0 + warp;

    const float4* gr = (const float4*)(g + (size_t)row * NN);

    float acc = 0.0f;
#pragma unroll
    for (int k = 0; k < 8; k++) {
        const int idx = lane + 32 * k;          // 0..255 float4 slots
        const float4 gv = gr[idx];
        const float4 cv = s_cs[idx];
        acc += exp2f(fmaf(gv.x, L2E, cv.x));
        acc += exp2f(fmaf(gv.y, L2E, cv.y));
        acc += exp2f(fmaf(gv.z, L2E, cv.z));
        acc += exp2f(fmaf(gv.w, L2E, cv.w));
    }
#pragma unroll
    for (int o = 16; o; o >>= 1)
        acc += __shfl_xor_sync(0xffffffffu, acc, o);

    if (lane == 0) d_rs[row] = -log2f(acc);
}

// ---------------------------------------------------------------------------
// Col pass: C[b,j] = -log2( sum_i exp2( g[b,i,j]*L2E + R[b,i] ) )
// Grid (4, 32): blockIdx.x = 256-wide j block, blockIdx.y = batch.
// Each thread owns one column j and walks all 1024 rows (coalesced across
// the warp: consecutive threads -> consecutive j). R[b,:] staged in smem.
__global__ __launch_bounds__(256) void col_pass_kernel(const float* __restrict__ g) {
    __shared__ float s_rs[NN];

    const int b = blockIdx.y;
    const int j = blockIdx.x * 256 + threadIdx.x;

#pragma unroll
    for (int k = 0; k < 4; k++)
        s_rs[threadIdx.x + 256 * k] = d_rs[(b << 10) + threadIdx.x + 256 * k];
    __syncthreads();

    const float* gp = g + (size_t)b * NN * NN + j;

    float acc = 0.0f;
#pragma unroll 16
    for (int i = 0; i < NN; i++) {
        acc += exp2f(fmaf(gp[(size_t)i * NN], L2E, s_rs[i]));
    }

    d_cs[(b << 10) + j] = -log2f(acc);
}

// ---------------------------------------------------------------------------
// Final: out[b,i,j] = exp2( g[b,i,j]*L2E + R[b,i] + C[b,j] )
__global__ __launch_bounds__(256) void final_pass_kernel(const float* __restrict__ g,
                                                         float* __restrict__ out) {
    __shared__ float4 s_cs[NN / 4];

    const int row0 = blockIdx.x * 8;
    const int b    = row0 >> 10;

    s_cs[threadIdx.x] = ((const float4*)(d_cs + (b << 10)))[threadIdx.x];
    __syncthreads();

    const int warp = threadIdx.x >> 5;
    const int lane = threadIdx.x & 31;
    const int row  = row0 + warp;

    const float  rv = d_rs[row];
    const float4* gr = (const float4*)(g + (size_t)row * NN);
    float4*      orw = (float4*)(out + (size_t)row * NN);

#pragma unroll
    for (int k = 0; k < 8; k++) {
        const int idx = lane + 32 * k;
        const float4 gv = gr[idx];
        const float4 cv = s_cs[idx];
        float4 o;
        o.x = exp2f(fmaf(gv.x, L2E, rv + cv.x));
        o.y = exp2f(fmaf(gv.y, L2E, rv + cv.y));
        o.z = exp2f(fmaf(gv.z, L2E, rv + cv.z));
        o.w = exp2f(fmaf(gv.w, L2E, rv + cv.w));
        orw[idx] = o;
    }
}

// ---------------------------------------------------------------------------
extern "C" void kernel_launch(void* const* d_in, const int* in_sizes, int n_in,
                              void* d_out, int out_size) {
    // Only the gumbel noise tensor matters (the score projection cancels in
    // the first row normalization). Identify it by element count B*N*N.
    const float* g = nullptr;
    for (int i = 0; i < n_in; i++) {
        if (in_sizes[i] == NB * NN * NN) { g = (const float*)d_in[i]; }
    }
    float* out = (float*)d_out;

    const int ROW_GRID = NB * NN / 8;   // 4096 CTAs, warp-per-row
    const dim3 COL_GRID(4, NB);         // 128 CTAs, full-column accumulate

    zero_cs_kernel<<<NB * NN / 256, 256>>>();

    for (int it = 0; it < 20; it++) {
        row_pass_kernel<<<ROW_GRID, 256>>>(g);   // axis=2 normalization
        col_pass_kernel<<<COL_GRID, 256>>>(g);   // axis=1 normalization
    }

    final_pass_kernel<<<ROW_GRID, 256>>>(g, out);
}

// round 7
// speedup vs baseline: 2.0436x; 2.0436x over previous
#include <cuda_runtime.h>
#include <math.h>

#define NB 32
#define NN 1024
#define L2E 1.4426950408889634f
#define ROWS_PER_CTA 16
#define FUSED_THREADS 512

// Scratch (device globals: no allocation allowed).
// Log2 domain: R = r*log2(e), C = c*log2(e).
__device__ float d_rs[NB * NN];
__device__ float d_cs[NB * NN];
__device__ float d_colacc[NB * NN];

// ---------------------------------------------------------------------------
__global__ __launch_bounds__(256) void zero_kernel() {
    const int idx = blockIdx.x * 256 + threadIdx.x;
    d_cs[idx] = 0.0f;
    d_colacc[idx] = 0.0f;
}

// ---------------------------------------------------------------------------
// Fused iteration kernel. Each CTA owns 16 complete rows of one batch.
// Phase A (warp-per-row): E_ij = exp2(g*L2E + C_j) -> smem; row sums -> R, 1/sum.
// Phase B (thread-per-2-cols): partial col sums sum_i E_ij * inv_i -> atomicAdd.
// True col sum of exp(g+r) is 2^{-C_j} * colacc_j; colfix folds that in.
__global__ __launch_bounds__(FUSED_THREADS, 3)
void fused_pass_kernel(const float* __restrict__ g) {
    extern __shared__ float smem[];
    float* s_E   = smem;                 // 16 * 1024 floats
    float* s_c   = smem + ROWS_PER_CTA * NN;  // 1024 floats
    float* s_inv = s_c + NN;             // 16 floats

    const int tid  = threadIdx.x;
    const int b    = blockIdx.x >> 6;            // 64 CTAs per batch
    const int rblk = (blockIdx.x & 63) * ROWS_PER_CTA;

    // stage C[b, :] (512 threads x 2)
    s_c[tid]       = d_cs[(b << 10) + tid];
    s_c[tid + 512] = d_cs[(b << 10) + tid + 512];
    __syncthreads();

    // ---- Phase A: warp per row ----
    const int warp = tid >> 5;
    const int lane = tid & 31;
    const int row  = (b << 10) + rblk + warp;

    const float4* gr = (const float4*)(g + (size_t)row * NN);
    float4*       er = (float4*)(s_E + warp * NN);
    const float4* c4 = (const float4*)s_c;

    float acc = 0.0f;
#pragma unroll
    for (int k = 0; k < 8; k++) {
        const int idx = lane + 32 * k;
        const float4 gv = gr[idx];
        const float4 cv = c4[idx];
        float4 e;
        e.x = exp2f(fmaf(gv.x, L2E, cv.x));
        e.y = exp2f(fmaf(gv.y, L2E, cv.y));
        e.z = exp2f(fmaf(gv.z, L2E, cv.z));
        e.w = exp2f(fmaf(gv.w, L2E, cv.w));
        er[idx] = e;
        acc += (e.x + e.y) + (e.z + e.w);
    }
#pragma unroll
    for (int o = 16; o; o >>= 1)
        acc += __shfl_xor_sync(0xffffffffu, acc, o);

    if (lane == 0) {
        d_rs[row]   = -log2f(acc);
        s_inv[warp] = __fdividef(1.0f, acc);
    }
    __syncthreads();

    // ---- Phase B: thread owns 2 adjacent columns ----
    float inv[ROWS_PER_CTA];
#pragma unroll
    for (int i = 0; i < ROWS_PER_CTA; i++) inv[i] = s_inv[i];

    float cx = 0.0f, cy = 0.0f;
#pragma unroll
    for (int i = 0; i < ROWS_PER_CTA; i++) {
        const float2 ev = ((const float2*)(s_E + i * NN))[tid];
        cx = fmaf(ev.x, inv[i], cx);
        cy = fmaf(ev.y, inv[i], cy);
    }
    float* ca = d_colacc + (b << 10) + 2 * tid;
    atomicAdd(ca,     cx);
    atomicAdd(ca + 1, cy);
}

// ---------------------------------------------------------------------------
// C_j <- C_j - log2(colacc_j); reset accumulator for the next iteration.
__global__ __launch_bounds__(256) void colfix_kernel() {
    const int idx = blockIdx.x * 256 + threadIdx.x;
    d_cs[idx] -= log2f(d_colacc[idx]);
    d_colacc[idx] = 0.0f;
}

// ---------------------------------------------------------------------------
// Final: out[b,i,j] = exp2( g*L2E + R_i + C_j ). Warp per row, 8 rows/CTA.
__global__ __launch_bounds__(256) void final_pass_kernel(const float* __restrict__ g,
                                                         float* __restrict__ out) {
    __shared__ float4 s_cs[NN / 4];

    const int row0 = blockIdx.x * 8;
    const int b    = row0 >> 10;

    s_cs[threadIdx.x] = ((const float4*)(d_cs + (b << 10)))[threadIdx.x];
    __syncthreads();

    const int warp = threadIdx.x >> 5;
    const int lane = threadIdx.x & 31;
    const int row  = row0 + warp;

    const float   rv = d_rs[row];
    const float4* gr = (const float4*)(g + (size_t)row * NN);
    float4*      orw = (float4*)(out + (size_t)row * NN);

#pragma unroll
    for (int k = 0; k < 8; k++) {
        const int idx = lane + 32 * k;
        const float4 gv = gr[idx];
        const float4 cv = s_cs[idx];
        float4 o;
        o.x = exp2f(fmaf(gv.x, L2E, rv + cv.x));
        o.y = exp2f(fmaf(gv.y, L2E, rv + cv.y));
        o.z = exp2f(fmaf(gv.z, L2E, rv + cv.z));
        o.w = exp2f(fmaf(gv.w, L2E, rv + cv.w));
        orw[idx] = o;
    }
}

// ---------------------------------------------------------------------------
extern "C" void kernel_launch(void* const* d_in, const int* in_sizes, int n_in,
                              void* d_out, int out_size) {
    // Only the gumbel tensor matters (projection cancels in first row norm).
    const float* g = nullptr;
    for (int i = 0; i < n_in; i++)
        if (in_sizes[i] == NB * NN * NN) g = (const float*)d_in[i];
    float* out = (float*)d_out;

    const int SMEM_BYTES = (ROWS_PER_CTA * NN + NN + ROWS_PER_CTA) * (int)sizeof(float);
    cudaFuncSetAttribute(fused_pass_kernel,
                         cudaFuncAttributeMaxDynamicSharedMemorySize, SMEM_BYTES);

    const int FUSED_GRID = NB * (NN / ROWS_PER_CTA);  // 2048 CTAs
    const int VEC_GRID   = NB * NN / 256;             // 128 CTAs
    const int ROW_GRID   = NB * NN / 8;               // 4096 CTAs

    zero_kernel<<<VEC_GRID, 256>>>();

    for (int it = 0; it < 20; it++) {
        fused_pass_kernel<<<FUSED_GRID, FUSED_THREADS, SMEM_BYTES>>>(g);
        colfix_kernel<<<VEC_GRID, 256>>>();
    }

    final_pass_kernel<<<ROW_GRID, 256>>>(g, out);
}